// round 11
// baseline (speedup 1.0000x reference)
#include <cuda_runtime.h>
#include <cuda_bf16.h>
#include <mma.h>
#include <math.h>
#include <stdint.h>
#include <string.h>

using namespace nvcuda;

#define NN     2048
#define NFEAT  512
#define NHID   128
#define NHEADS 4
#define NP     3
#define PH     (NP*NHEADS)
#define ALPHA  0.2f

// ---------------- device scratch ----------------
__device__ float g_m[NP * NN * (NHEADS*NHID)];
__device__ __align__(16) __nv_bfloat16 g_hThi[PH * NHID * NN];
__device__ __align__(16) __nv_bfloat16 g_hTlo[PH * NHID * NN];
__device__ __align__(16) __nv_bfloat16 g_xhi[NN * NFEAT];
__device__ __align__(16) __nv_bfloat16 g_xlo[NN * NFEAT];
__device__ __align__(16) __nv_bfloat16 g_Whi[PH * NFEAT * NHID];
__device__ __align__(16) __nv_bfloat16 g_Wlo[PH * NFEAT * NHID];
__device__ float4  g_sE4[PH * NN];
__device__ float4  g_dE4[PH * NN];
__device__ uint32_t g_maskN[NP * NN * (NN/32)];
__device__ float g_scores[NP];

static __device__ __forceinline__ uint32_t b2u(__nv_bfloat162 h) {
    uint32_t u; memcpy(&u, &h, 4); return u;
}
static __device__ __forceinline__ uint32_t smem_u32(const void* p) {
    uint32_t a;
    asm("{ .reg .u64 t; cvta.to.shared.u64 t, %1; cvt.u32.u64 %0, t; }" : "=r"(a) : "l"(p));
    return a;
}
#define MBAR_INIT(a, c)  asm volatile("mbarrier.init.shared.b64 [%0], %1;" :: "r"((uint32_t)(a)), "r"((uint32_t)(c)) : "memory")
#define MBAR_ARRIVE(a)   asm volatile("mbarrier.arrive.shared.b64 _, [%0];" :: "r"((uint32_t)(a)) : "memory")
#define MBAR_WAIT(a, par) do { \
    uint32_t _m = (uint32_t)(a), _p = (uint32_t)(par), _d; \
    asm volatile("{\n\t.reg .pred p;\n\tmbarrier.try_wait.parity.acquire.cta.shared::cta.b64 p, [%1], %2;\n\tselp.b32 %0, 1, 0, p;\n\t}" \
                 : "=r"(_d) : "r"(_m), "r"(_p) : "memory"); \
    if (!_d) { \
        asm volatile("{\n\t.reg .pred P1;\n\tWL_%=:\n\tmbarrier.try_wait.parity.acquire.cta.shared::cta.b64 P1, [%0], %1, 0x989680;\n\t@P1 bra.uni WD_%=;\n\tbra.uni WL_%=;\n\tWD_%=:\n\t}" \
                     :: "r"(_m), "r"(_p) : "memory"); \
    } \
} while (0)
#define CP_ASYNC16(smem, gptr) \
    asm volatile("cp.async.cg.shared.global [%0], [%1], 16;" :: "r"((uint32_t)(smem)), "l"(gptr) : "memory")
#define CP_COMMIT()  asm volatile("cp.async.commit_group;" ::: "memory")
#define CP_WAIT0()   asm volatile("cp.async.wait_group 0;" ::: "memory")
#define CP_WAIT1()   asm volatile("cp.async.wait_group 1;" ::: "memory")

// ---------------- k0 ----------------
__global__ void k0_init() { if (threadIdx.x < NP) g_scores[threadIdx.x] = 0.f; }

// ---------------- k_prep: fused split(x, W_node) + adjacency bitmask ----------
#define NXE (NN * NFEAT)
#define NWE (PH * NFEAT * NHID)
#define SPLIT_BLOCKS ((NXE + NWE + 255) / 256)
#define PACK_BLOCKS  (NP * NN * 64 / 8)
__global__ __launch_bounds__(256) void k_prep(const float* __restrict__ x,
                                              const float* __restrict__ Wn,
                                              const float* __restrict__ adjs) {
    // pack part (every block)
    {
        int g = blockIdx.x * 8 + (threadIdx.x >> 5);
        int lane = threadIdx.x & 31;
        float v = adjs[(size_t)g * 32 + lane];
        uint32_t b = __ballot_sync(0xffffffffu, v > 0.f);
        if (lane == 0) g_maskN[g] = b;
    }
    // split part (first SPLIT_BLOCKS blocks)
    if (blockIdx.x < SPLIT_BLOCKS) {
        int i = blockIdx.x * 256 + threadIdx.x;
        if (i < NXE) {
            float v = x[i];
            __nv_bfloat16 h = __float2bfloat16_rn(v);
            g_xhi[i] = h;
            g_xlo[i] = __float2bfloat16_rn(v - __bfloat162float(h));
        }
        int j = i - NXE;
        if (j >= 0 && j < NWE) {
            float v = Wn[j];
            __nv_bfloat16 h = __float2bfloat16_rn(v);
            g_Whi[j] = h;
            g_Wlo[j] = __float2bfloat16_rn(v - __bfloat162float(h));
        }
    }
}

// ---------------- k1: 3-stage cp.async pipelined WMMA node GEMM ---------------
// 256 thr, 128x128 tile, K=512 in 8 chunks of 64.
// stage (71680 B): AH@0 (128x72 bf16), AL@18432, BH@36864 (64x136), BL@54272.
// 3 stages = 215040. a_sh@215040, red_s@216064, red_d@217088. C aliases stage 0.
#define K1_LDA   72
#define K1_LDB   136
#define K1_LDC   132
#define K1_ST    71680
#define K1_OAL   18432
#define K1_OBH   36864
#define K1_OBL   54272
#define K1_OAN   215040
#define K1_ORS   216064
#define K1_ORD   217088
#define K1_SMEM_BYTES 218112

__global__ __launch_bounds__(256) void k1_node_wmma(const float* __restrict__ an) {
    extern __shared__ char sm[];
    uint32_t sbase = smem_u32(sm);
    float* csh   = (float*)(sm);
    float* a_sh  = (float*)(sm + K1_OAN);
    float* red_s = (float*)(sm + K1_ORS);
    float* red_d = (float*)(sm + K1_ORD);

    int ph   = blockIdx.y;
    int row0 = blockIdx.x * 128;
    int tid  = threadIdx.x;
    int warp = tid >> 5;
    int wr   = warp >> 1;
    int wc   = warp & 1;

    int rA = tid >> 1, hA = tid & 1;    // A: row, k-half(32)
    int rB = tid >> 2, qB = tid & 3;    // B: k-row, n-quarter(32)

    const char* xsrcH = (const char*)(g_xhi + (size_t)(row0 + rA) * NFEAT + hA * 32);
    const char* xsrcL = (const char*)(g_xlo + (size_t)(row0 + rA) * NFEAT + hA * 32);
    const char* wsrcH = (const char*)(g_Whi + (size_t)ph * NFEAT * NHID + (size_t)rB * NHID + qB * 32);
    const char* wsrcL = (const char*)(g_Wlo + (size_t)ph * NFEAT * NHID + (size_t)rB * NHID + qB * 32);
    uint32_t adstH = sbase + rA * (K1_LDA * 2) + hA * 64;
    uint32_t adstL = adstH + K1_OAL;
    uint32_t bdstH = sbase + K1_OBH + rB * (K1_LDB * 2) + qB * 64;
    uint32_t bdstL = bdstH + (K1_OBL - K1_OBH);

#define K1_ISSUE(c) do { \
    int _s = (c) % 3; uint32_t _sb = _s * K1_ST; size_t _ko = (size_t)(c) * 64; \
    const char* _xh = xsrcH + _ko * 2; const char* _xl = xsrcL + _ko * 2; \
    const char* _wh = wsrcH + _ko * NHID * 2; const char* _wl = wsrcL + _ko * NHID * 2; \
    CP_ASYNC16(adstH + _sb,      _xh);      CP_ASYNC16(adstH + _sb + 16, _xh + 16); \
    CP_ASYNC16(adstH + _sb + 32, _xh + 32); CP_ASYNC16(adstH + _sb + 48, _xh + 48); \
    CP_ASYNC16(adstL + _sb,      _xl);      CP_ASYNC16(adstL + _sb + 16, _xl + 16); \
    CP_ASYNC16(adstL + _sb + 32, _xl + 32); CP_ASYNC16(adstL + _sb + 48, _xl + 48); \
    CP_ASYNC16(bdstH + _sb,      _wh);      CP_ASYNC16(bdstH + _sb + 16, _wh + 16); \
    CP_ASYNC16(bdstH + _sb + 32, _wh + 32); CP_ASYNC16(bdstH + _sb + 48, _wh + 48); \
    CP_ASYNC16(bdstL + _sb,      _wl);      CP_ASYNC16(bdstL + _sb + 16, _wl + 16); \
    CP_ASYNC16(bdstL + _sb + 32, _wl + 32); CP_ASYNC16(bdstL + _sb + 48, _wl + 48); \
    CP_COMMIT(); \
} while (0)

    wmma::fragment<wmma::accumulator, 16, 16, 16, float> c[2][4];
#pragma unroll
    for (int i = 0; i < 2; i++)
#pragma unroll
        for (int j = 0; j < 4; j++) wmma::fill_fragment(c[i][j], 0.f);

    K1_ISSUE(0);
    K1_ISSUE(1);

    for (int ch = 0; ch < 8; ch++) {
        int s = ch % 3;
        if (ch < 7) { CP_WAIT1(); } else { CP_WAIT0(); }
        __syncthreads();
        if (ch + 2 < 8) K1_ISSUE(ch + 2);

        __nv_bfloat16* ash = (__nv_bfloat16*)(sm + s * K1_ST);
        __nv_bfloat16* asl = (__nv_bfloat16*)(sm + s * K1_ST + K1_OAL);
        __nv_bfloat16* bsh = (__nv_bfloat16*)(sm + s * K1_ST + K1_OBH);
        __nv_bfloat16* bsl = (__nv_bfloat16*)(sm + s * K1_ST + K1_OBL);

#pragma unroll
        for (int ks = 0; ks < 4; ks++) {
            int kk = ks * 16;
            wmma::fragment<wmma::matrix_a, 16, 16, 16, __nv_bfloat16, wmma::row_major> ah[2], al[2];
#pragma unroll
            for (int i = 0; i < 2; i++) {
                wmma::load_matrix_sync(ah[i], ash + (wr * 32 + i * 16) * K1_LDA + kk, K1_LDA);
                wmma::load_matrix_sync(al[i], asl + (wr * 32 + i * 16) * K1_LDA + kk, K1_LDA);
            }
#pragma unroll
            for (int j = 0; j < 4; j++) {
                wmma::fragment<wmma::matrix_b, 16, 16, 16, __nv_bfloat16, wmma::row_major> bh, bl;
                wmma::load_matrix_sync(bh, bsh + kk * K1_LDB + wc * 64 + j * 16, K1_LDB);
                wmma::load_matrix_sync(bl, bsl + kk * K1_LDB + wc * 64 + j * 16, K1_LDB);
#pragma unroll
                for (int i = 0; i < 2; i++) {
                    wmma::mma_sync(c[i][j], ah[i], bh, c[i][j]);
                    wmma::mma_sync(c[i][j], ah[i], bl, c[i][j]);
                    wmma::mma_sync(c[i][j], al[i], bh, c[i][j]);
                }
            }
        }
        __syncthreads();   // all warps done with stage s before cp.async reuses it
    }

    a_sh[tid] = an[(size_t)ph * 2 * NHID + tid];
#pragma unroll
    for (int i = 0; i < 2; i++)
#pragma unroll
        for (int j = 0; j < 4; j++)
            wmma::store_matrix_sync(csh + (wr * 32 + i * 16) * K1_LDC + wc * 64 + j * 16,
                                    c[i][j], K1_LDC, wmma::mem_row_major);
    __syncthreads();

    {
        int r = tid & 127, hf = tid >> 7;
        float ps = 0.f, pd = 0.f;
        const float* row = csh + r * K1_LDC + hf * 64;
#pragma unroll
        for (int i = 0; i < 64; i++) {
            float v = row[i];
            ps += v * a_sh[hf * 64 + i];
            pd += v * a_sh[NHID + hf * 64 + i];
        }
        red_s[hf * 128 + r] = ps;
        red_d[hf * 128 + r] = pd;
    }

    {
        int d = tid & 127, hf = tid >> 7;
        __nv_bfloat16* dstH = g_hThi + ((size_t)ph * NHID + d) * NN + row0 + hf * 64;
        __nv_bfloat16* dstL = g_hTlo + ((size_t)ph * NHID + d) * NN + row0 + hf * 64;
#pragma unroll
        for (int i = 0; i < 64; i += 4) {
            float v0 = csh[(hf * 64 + i    ) * K1_LDC + d];
            float v1 = csh[(hf * 64 + i + 1) * K1_LDC + d];
            float v2 = csh[(hf * 64 + i + 2) * K1_LDC + d];
            float v3 = csh[(hf * 64 + i + 3) * K1_LDC + d];
            __nv_bfloat162 h01 = __float22bfloat162_rn(make_float2(v0, v1));
            __nv_bfloat162 h23 = __float22bfloat162_rn(make_float2(v2, v3));
            __nv_bfloat162 l01 = __float22bfloat162_rn(make_float2(v0 - __bfloat162float(h01.x),
                                                                   v1 - __bfloat162float(h01.y)));
            __nv_bfloat162 l23 = __float22bfloat162_rn(make_float2(v2 - __bfloat162float(h23.x),
                                                                   v3 - __bfloat162float(h23.y)));
            *(uint2*)(dstH + i) = make_uint2(b2u(h01), b2u(h23));
            *(uint2*)(dstL + i) = make_uint2(b2u(l01), b2u(l23));
        }
    }
    __syncthreads();
    if (tid < 128) {
        float s = red_s[tid] + red_s[128 + tid];
        float d = red_d[tid] + red_d[128 + tid];
        int idx = ph * NN + row0 + tid;
        g_sE4[idx] = make_float4(s, expf(s), expf(ALPHA * s), 0.f);
        g_dE4[idx] = make_float4(d, expf(d), expf(ALPHA * d), 0.f);
    }
}

// ---------------- k3: warp-specialized, 3-stage (unchanged from R10) ----------
#define LDA      72
#define LDC      132
#define NSTAGE   3
#define ST_STRIDE 73728
#define OFF_SAL  18432
#define OFF_SBH  36864
#define OFF_SBL  55296
#define OFF_DE   221184
#define OFF_ROW  224256
#define OFF_MBAR 224768
#define K3_SMEM_BYTES 225280

__global__ __launch_bounds__(384, 1) void k3_attn_wmma() {
    extern __shared__ char sm[];
    float*  csh  = (float*)(sm);
    float*  rsb  = (float*)(sm + OFF_ROW);
    uint32_t sbase = smem_u32(sm);
    uint32_t mbar = sbase + OFF_MBAR;

    int ph   = blockIdx.y;
    int p    = ph >> 2, head = ph & 3;
    int row0 = blockIdx.x * 128;
    int tid  = threadIdx.x;

    if (tid == 0) {
#pragma unroll
        for (int s = 0; s < NSTAGE; s++) {
            MBAR_INIT(mbar + s * 8, 128);
            MBAR_INIT(mbar + 24 + s * 8, 256);
        }
    }
    __syncthreads();

    wmma::fragment<wmma::accumulator, 16, 16, 16, float> c[2][4];

    if (tid < 128) {
        // producer
        int r = tid;
        float4 sE = g_sE4[ph * NN + row0 + r];
        const float s_r = sE.x, Es_r = sE.y, Eas_r = sE.z;
        float rs_local = 0.f;
        uint32_t phE[NSTAGE] = {0, 0, 0};

        for (int chk = 0; chk < 32; chk++) {
            int s = chk % NSTAGE;
            int m0 = chk * 64;
            if (chk >= NSTAGE) { MBAR_WAIT(mbar + 24 + s * 8, phE[s]); phE[s] ^= 1; }

            {
                const char* srcH = (const char*)(g_hThi + ((size_t)ph * NHID + r) * NN + m0);
                const char* srcL = (const char*)(g_hTlo + ((size_t)ph * NHID + r) * NN + m0);
                uint32_t dstH = sbase + s * ST_STRIDE + OFF_SBH + r * (LDA * 2);
                uint32_t dstL = sbase + s * ST_STRIDE + OFF_SBL + r * (LDA * 2);
#pragma unroll
                for (int k = 0; k < 8; k++) {
                    CP_ASYNC16(dstH + k * 16, srcH + k * 16);
                    CP_ASYNC16(dstL + k * 16, srcL + k * 16);
                }
                CP_COMMIT();
            }
            float4* dEs = (float4*)(sm + OFF_DE + s * 1024);
            if (tid < 64) dEs[tid] = g_dE4[ph * NN + m0 + tid];
            asm volatile("bar.sync 1, 128;" ::: "memory");

            {
                __nv_bfloat16* ah_ = (__nv_bfloat16*)(sm + s * ST_STRIDE) + r * LDA;
                __nv_bfloat16* al_ = (__nv_bfloat16*)(sm + s * ST_STRIDE + OFF_SAL) + r * LDA;
                const uint32_t* mwp = &g_maskN[((size_t)p * NN + row0 + r) * 64 + chk * 2];
#pragma unroll
                for (int hf = 0; hf < 2; hf++) {
                    uint32_t mw = mwp[hf];
#pragma unroll
                    for (int g4 = 0; g4 < 4; g4++) {
                        float v[8];
#pragma unroll
                        for (int j = 0; j < 8; j++) {
                            float4 q = dEs[hf * 32 + g4 * 8 + j];
                            float t = s_r + q.x;
                            float w = (t > 0.f) ? (Es_r * q.y) : (Eas_r * q.z);
                            v[j] = ((mw >> (g4 * 8 + j)) & 1u) ? w : 0.f;
                            rs_local += v[j];
                        }
                        uint32_t hw[4], lw[4];
#pragma unroll
                        for (int jj = 0; jj < 4; jj++) {
                            __nv_bfloat162 h2 = __float22bfloat162_rn(make_float2(v[2*jj], v[2*jj+1]));
                            __nv_bfloat162 l2 = __float22bfloat162_rn(
                                make_float2(v[2*jj]   - __bfloat162float(h2.x),
                                            v[2*jj+1] - __bfloat162float(h2.y)));
                            hw[jj] = b2u(h2); lw[jj] = b2u(l2);
                        }
                        *(uint4*)(ah_ + hf * 32 + g4 * 8) = make_uint4(hw[0], hw[1], hw[2], hw[3]);
                        *(uint4*)(al_ + hf * 32 + g4 * 8) = make_uint4(lw[0], lw[1], lw[2], lw[3]);
                    }
                }
            }
            CP_WAIT0();
            MBAR_ARRIVE(mbar + s * 8);
        }
        rsb[r] = rs_local;
    } else {
        // consumer
        int cw = (tid >> 5) - 4;
        int wr = cw >> 1;
        int wc = cw & 1;
        uint32_t phF[NSTAGE] = {0, 0, 0};

#pragma unroll
        for (int i = 0; i < 2; i++)
#pragma unroll
            for (int j = 0; j < 4; j++) wmma::fill_fragment(c[i][j], 0.f);

        for (int chk = 0; chk < 32; chk++) {
            int s = chk % NSTAGE;
            MBAR_WAIT(mbar + s * 8, phF[s]); phF[s] ^= 1;

            __nv_bfloat16* ash = (__nv_bfloat16*)(sm + s * ST_STRIDE);
            __nv_bfloat16* asl = (__nv_bfloat16*)(sm + s * ST_STRIDE + OFF_SAL);
            __nv_bfloat16* bsh = (__nv_bfloat16*)(sm + s * ST_STRIDE + OFF_SBH);
            __nv_bfloat16* bsl = (__nv_bfloat16*)(sm + s * ST_STRIDE + OFF_SBL);

            wmma::fragment<wmma::matrix_a, 16, 16, 16, __nv_bfloat16, wmma::row_major> ah[2][2], al[2][2];
#pragma unroll
            for (int i = 0; i < 2; i++) {
                wmma::load_matrix_sync(ah[0][i], ash + (wr * 32 + i * 16) * LDA, LDA);
                wmma::load_matrix_sync(al[0][i], asl + (wr * 32 + i * 16) * LDA, LDA);
            }
#pragma unroll
            for (int ks = 0; ks < 4; ks++) {
                int kk = ks * 16;
                int cur = ks & 1, nxt = cur ^ 1;
                wmma::fragment<wmma::matrix_b, 16, 16, 16, __nv_bfloat16, wmma::col_major> bh[4], bl[4];
#pragma unroll
                for (int j = 0; j < 4; j++) {
                    wmma::load_matrix_sync(bh[j], bsh + (wc * 64 + j * 16) * LDA + kk, LDA);
                    wmma::load_matrix_sync(bl[j], bsl + (wc * 64 + j * 16) * LDA + kk, LDA);
                }
                if (ks < 3) {
#pragma unroll
                    for (int i = 0; i < 2; i++) {
                        wmma::load_matrix_sync(ah[nxt][i], ash + (wr * 32 + i * 16) * LDA + kk + 16, LDA);
                        wmma::load_matrix_sync(al[nxt][i], asl + (wr * 32 + i * 16) * LDA + kk + 16, LDA);
                    }
                }
#pragma unroll
                for (int j = 0; j < 4; j++)
#pragma unroll
                    for (int i = 0; i < 2; i++) {
                        wmma::mma_sync(c[i][j], ah[cur][i], bh[j], c[i][j]);
                        wmma::mma_sync(c[i][j], ah[cur][i], bl[j], c[i][j]);
                        wmma::mma_sync(c[i][j], al[cur][i], bh[j], c[i][j]);
                    }
            }
            MBAR_ARRIVE(mbar + 24 + s * 8);
        }
    }

    __syncthreads();
    if (tid >= 128) {
        int cw = (tid >> 5) - 4;
        int wr = cw >> 1, wc = cw & 1;
#pragma unroll
        for (int i = 0; i < 2; i++)
#pragma unroll
            for (int j = 0; j < 4; j++)
                wmma::store_matrix_sync(csh + (wr * 32 + i * 16) * LDC + wc * 64 + j * 16,
                                        c[i][j], LDC, wmma::mem_row_major);
    }
    __syncthreads();

    if (tid < 256) {
        int rr  = tid & 127;
        int chf = tid >> 7;
        float rsum = rsb[rr];
        float inv = (rsum > 0.f) ? (1.f / rsum) : 0.f;
        const float* src = csh + rr * LDC + chf * 64;
        float* dst = g_m + ((size_t)p * NN + row0 + rr) * (NHEADS * NHID) + head * NHID + chf * 64;
#pragma unroll
        for (int cc = 0; cc < 64; cc += 4) {
            float f0 = src[cc]   * inv;
            float f1 = src[cc+1] * inv;
            float f2 = src[cc+2] * inv;
            float f3 = src[cc+3] * inv;
            f0 = (f0 > 0.f) ? f0 : expm1f(f0);
            f1 = (f1 > 0.f) ? f1 : expm1f(f1);
            f2 = (f2 > 0.f) ? f2 : expm1f(f2);
            f3 = (f3 > 0.f) ? f3 : expm1f(f3);
            *(float4*)(dst + cc) = make_float4(f0, f1, f2, f3);
        }
    }
}

// ---------------- k4: semantic scores ----------------
__global__ __launch_bounds__(256) void k4_sem(const float* __restrict__ Wsem,
                                              const float* __restrict__ bsem,
                                              const float* __restrict__ qsem) {
    __shared__ float msh[32][65];
    __shared__ float wsh[64 * 128];
    __shared__ float red[8];
    int row0 = blockIdx.x * 32;
    int pidx = row0 / NN;
    int tid = threadIdx.x;
    int rg = tid >> 5;
    int cg = tid & 31;

    float acc[4][4];
#pragma unroll
    for (int r = 0; r < 4; r++)
#pragma unroll
        for (int c = 0; c < 4; c++) acc[r][c] = 0.f;

    for (int k0 = 0; k0 < 512; k0 += 64) {
        for (int i = tid; i < 32 * 64; i += 256)
            msh[i >> 6][i & 63] = g_m[(size_t)(row0 + (i >> 6)) * 512 + k0 + (i & 63)];
        for (int i = tid * 4; i < 64 * 128; i += 1024)
            *(float4*)&wsh[i] = *(const float4*)&Wsem[(size_t)k0 * 128 + i];
        __syncthreads();
#pragma unroll
        for (int k = 0; k < 64; k++) {
            float mv[4];
#pragma unroll
            for (int r = 0; r < 4; r++) mv[r] = msh[rg * 4 + r][k];
            float4 wv = *(float4*)&wsh[k * 128 + cg * 4];
            float wva[4] = {wv.x, wv.y, wv.z, wv.w};
#pragma unroll
            for (int r = 0; r < 4; r++)
#pragma unroll
                for (int c = 0; c < 4; c++) acc[r][c] += mv[r] * wva[c];
        }
        __syncthreads();
    }
    float part = 0.f;
#pragma unroll
    for (int c = 0; c < 4; c++) {
        int col = cg * 4 + c;
        float b = bsem[col], q = qsem[col];
#pragma unroll
        for (int r = 0; r < 4; r++)
            part += tanhf(acc[r][c] + b) * q;
    }
#pragma unroll
    for (int off = 16; off; off >>= 1)
        part += __shfl_xor_sync(0xffffffffu, part, off);
    if ((tid & 31) == 0) red[tid >> 5] = part;
    __syncthreads();
    if (tid == 0) {
        float tot = 0.f;
#pragma unroll
        for (int i = 0; i < 8; i++) tot += red[i];
        atomicAdd(&g_scores[pidx], tot);
    }
}

// ---------------- k6 ----------------
__global__ __launch_bounds__(256) void k6_out(float* __restrict__ out) {
    __shared__ float w[NP];
    if (threadIdx.x == 0) {
        float s0 = g_scores[0] * (1.f / NN);
        float s1 = g_scores[1] * (1.f / NN);
        float s2 = g_scores[2] * (1.f / NN);
        float mx = fmaxf(s0, fmaxf(s1, s2));
        float e0 = expf(s0 - mx), e1 = expf(s1 - mx), e2 = expf(s2 - mx);
        float inv = 1.f / (e0 + e1 + e2);
        w[0] = e0 * inv; w[1] = e1 * inv; w[2] = e2 * inv;
    }
    __syncthreads();
    size_t i = (size_t)blockIdx.x * blockDim.x + threadIdx.x;
    const size_t stride = (size_t)NN * 512;
    out[i] = w[0] * g_m[i] + w[1] * g_m[stride + i] + w[2] * g_m[2 * stride + i];
}

// ---------------- launch ----------------
extern "C" void kernel_launch(void* const* d_in, const int* in_sizes, int n_in,
                              void* d_out, int out_size) {
    const float* x    = (const float*)d_in[0];
    const float* adjs = (const float*)d_in[1];
    const float* Wn   = (const float*)d_in[2];
    const float* an   = (const float*)d_in[3];
    const float* Wsem = (const float*)d_in[4];
    const float* bsem = (const float*)d_in[5];
    const float* qsem = (const float*)d_in[6];
    float* out = (float*)d_out;

    cudaFuncSetAttribute(k3_attn_wmma, cudaFuncAttributeMaxDynamicSharedMemorySize, K3_SMEM_BYTES);
    cudaFuncSetAttribute(k1_node_wmma, cudaFuncAttributeMaxDynamicSharedMemorySize, K1_SMEM_BYTES);

    k0_init<<<1, 32>>>();                                        // 1
    k_prep<<<PACK_BLOCKS, 256>>>(x, Wn, adjs);                   // 2
    k1_node_wmma<<<dim3(NN / 128, PH), 256, K1_SMEM_BYTES>>>(an);// 3
    k3_attn_wmma<<<dim3(NN / 128, PH), 384, K3_SMEM_BYTES>>>();  // 4  <- profiled slot
    k4_sem<<<(NP * NN) / 32, 256>>>(Wsem, bsem, qsem);           // 5
    k6_out<<<(NN * 512) / 256, 256>>>(out);                      // 6
}

// round 12
// speedup vs baseline: 1.0052x; 1.0052x over previous
#include <cuda_runtime.h>
#include <cuda_bf16.h>
#include <mma.h>
#include <math.h>
#include <stdint.h>
#include <string.h>

using namespace nvcuda;

#define NN     2048
#define NFEAT  512
#define NHID   128
#define NHEADS 4
#define NP     3
#define PH     (NP*NHEADS)
#define ALPHA  0.2f

// ---------------- device scratch ----------------
__device__ float g_m[NP * NN * (NHEADS*NHID)];
__device__ __align__(16) __nv_bfloat16 g_hThi[PH * NHID * NN];
__device__ __align__(16) __nv_bfloat16 g_hTlo[PH * NHID * NN];
__device__ __align__(16) __nv_bfloat16 g_xhi[NN * NFEAT];
__device__ __align__(16) __nv_bfloat16 g_xlo[NN * NFEAT];
__device__ __align__(16) __nv_bfloat16 g_Whi[PH * NFEAT * NHID];
__device__ __align__(16) __nv_bfloat16 g_Wlo[PH * NFEAT * NHID];
__device__ float4  g_sE4[PH * NN];
__device__ float4  g_dE4[PH * NN];
__device__ uint32_t g_maskN[NP * NN * (NN/32)];
__device__ float g_scores[NP];

static __device__ __forceinline__ uint32_t b2u(__nv_bfloat162 h) {
    uint32_t u; memcpy(&u, &h, 4); return u;
}
static __device__ __forceinline__ uint32_t smem_u32(const void* p) {
    uint32_t a;
    asm("{ .reg .u64 t; cvta.to.shared.u64 t, %1; cvt.u32.u64 %0, t; }" : "=r"(a) : "l"(p));
    return a;
}
#define MBAR_INIT(a, c)  asm volatile("mbarrier.init.shared.b64 [%0], %1;" :: "r"((uint32_t)(a)), "r"((uint32_t)(c)) : "memory")
#define MBAR_ARRIVE(a)   asm volatile("mbarrier.arrive.shared.b64 _, [%0];" :: "r"((uint32_t)(a)) : "memory")
#define MBAR_WAIT(a, par) do { \
    uint32_t _m = (uint32_t)(a), _p = (uint32_t)(par), _d; \
    asm volatile("{\n\t.reg .pred p;\n\tmbarrier.try_wait.parity.acquire.cta.shared::cta.b64 p, [%1], %2;\n\tselp.b32 %0, 1, 0, p;\n\t}" \
                 : "=r"(_d) : "r"(_m), "r"(_p) : "memory"); \
    if (!_d) { \
        asm volatile("{\n\t.reg .pred P1;\n\tWL_%=:\n\tmbarrier.try_wait.parity.acquire.cta.shared::cta.b64 P1, [%0], %1, 0x989680;\n\t@P1 bra.uni WD_%=;\n\tbra.uni WL_%=;\n\tWD_%=:\n\t}" \
                     :: "r"(_m), "r"(_p) : "memory"); \
    } \
} while (0)
#define CP_ASYNC16(smem, gptr) \
    asm volatile("cp.async.cg.shared.global [%0], [%1], 16;" :: "r"((uint32_t)(smem)), "l"(gptr) : "memory")
#define CP_COMMIT()  asm volatile("cp.async.commit_group;" ::: "memory")
#define CP_WAIT0()   asm volatile("cp.async.wait_group 0;" ::: "memory")
#define CP_WAIT1()   asm volatile("cp.async.wait_group 1;" ::: "memory")

// ---------------- k0 ----------------
__global__ void k0_init() { if (threadIdx.x < NP) g_scores[threadIdx.x] = 0.f; }

// ---------------- k_prep: fused split + pack ----------
#define NXE (NN * NFEAT)
#define NWE (PH * NFEAT * NHID)
#define SPLIT_BLOCKS ((NXE + NWE + 255) / 256)
#define PACK_BLOCKS  (NP * NN * 64 / 8)
__global__ __launch_bounds__(256) void k_prep(const float* __restrict__ x,
                                              const float* __restrict__ Wn,
                                              const float* __restrict__ adjs) {
    {
        int g = blockIdx.x * 8 + (threadIdx.x >> 5);
        int lane = threadIdx.x & 31;
        float v = adjs[(size_t)g * 32 + lane];
        uint32_t b = __ballot_sync(0xffffffffu, v > 0.f);
        if (lane == 0) g_maskN[g] = b;
    }
    if (blockIdx.x < SPLIT_BLOCKS) {
        int i = blockIdx.x * 256 + threadIdx.x;
        if (i < NXE) {
            float v = x[i];
            __nv_bfloat16 h = __float2bfloat16_rn(v);
            g_xhi[i] = h;
            g_xlo[i] = __float2bfloat16_rn(v - __bfloat162float(h));
        }
        int j = i - NXE;
        if (j >= 0 && j < NWE) {
            float v = Wn[j];
            __nv_bfloat16 h = __float2bfloat16_rn(v);
            g_Whi[j] = h;
            g_Wlo[j] = __float2bfloat16_rn(v - __bfloat162float(h));
        }
    }
}

// ---------------- k1: 3-stage cp.async pipelined WMMA node GEMM ---------------
#define K1_LDA   72
#define K1_LDB   136
#define K1_LDC   132
#define K1_ST    71680
#define K1_OAL   18432
#define K1_OBH   36864
#define K1_OBL   54272
#define K1_OAN   215040
#define K1_ORS   216064
#define K1_ORD   217088
#define K1_SMEM_BYTES 218112

__global__ __launch_bounds__(256) void k1_node_wmma(const float* __restrict__ an) {
    extern __shared__ char sm[];
    uint32_t sbase = smem_u32(sm);
    float* csh   = (float*)(sm);
    float* a_sh  = (float*)(sm + K1_OAN);
    float* red_s = (float*)(sm + K1_ORS);
    float* red_d = (float*)(sm + K1_ORD);

    int ph   = blockIdx.y;
    int row0 = blockIdx.x * 128;
    int tid  = threadIdx.x;
    int warp = tid >> 5;
    int wr   = warp >> 1;
    int wc   = warp & 1;

    int rA = tid >> 1, hA = tid & 1;
    int rB = tid >> 2, qB = tid & 3;

    const char* xsrcH = (const char*)(g_xhi + (size_t)(row0 + rA) * NFEAT + hA * 32);
    const char* xsrcL = (const char*)(g_xlo + (size_t)(row0 + rA) * NFEAT + hA * 32);
    const char* wsrcH = (const char*)(g_Whi + (size_t)ph * NFEAT * NHID + (size_t)rB * NHID + qB * 32);
    const char* wsrcL = (const char*)(g_Wlo + (size_t)ph * NFEAT * NHID + (size_t)rB * NHID + qB * 32);
    uint32_t adstH = sbase + rA * (K1_LDA * 2) + hA * 64;
    uint32_t adstL = adstH + K1_OAL;
    uint32_t bdstH = sbase + K1_OBH + rB * (K1_LDB * 2) + qB * 64;
    uint32_t bdstL = bdstH + (K1_OBL - K1_OBH);

#define K1_ISSUE(c) do { \
    int _s = (c) % 3; uint32_t _sb = _s * K1_ST; size_t _ko = (size_t)(c) * 64; \
    const char* _xh = xsrcH + _ko * 2; const char* _xl = xsrcL + _ko * 2; \
    const char* _wh = wsrcH + _ko * NHID * 2; const char* _wl = wsrcL + _ko * NHID * 2; \
    CP_ASYNC16(adstH + _sb,      _xh);      CP_ASYNC16(adstH + _sb + 16, _xh + 16); \
    CP_ASYNC16(adstH + _sb + 32, _xh + 32); CP_ASYNC16(adstH + _sb + 48, _xh + 48); \
    CP_ASYNC16(adstL + _sb,      _xl);      CP_ASYNC16(adstL + _sb + 16, _xl + 16); \
    CP_ASYNC16(adstL + _sb + 32, _xl + 32); CP_ASYNC16(adstL + _sb + 48, _xl + 48); \
    CP_ASYNC16(bdstH + _sb,      _wh);      CP_ASYNC16(bdstH + _sb + 16, _wh + 16); \
    CP_ASYNC16(bdstH + _sb + 32, _wh + 32); CP_ASYNC16(bdstH + _sb + 48, _wh + 48); \
    CP_ASYNC16(bdstL + _sb,      _wl);      CP_ASYNC16(bdstL + _sb + 16, _wl + 16); \
    CP_ASYNC16(bdstL + _sb + 32, _wl + 32); CP_ASYNC16(bdstL + _sb + 48, _wl + 48); \
    CP_COMMIT(); \
} while (0)

    wmma::fragment<wmma::accumulator, 16, 16, 16, float> c[2][4];
#pragma unroll
    for (int i = 0; i < 2; i++)
#pragma unroll
        for (int j = 0; j < 4; j++) wmma::fill_fragment(c[i][j], 0.f);

    K1_ISSUE(0);
    K1_ISSUE(1);

    for (int ch = 0; ch < 8; ch++) {
        int s = ch % 3;
        if (ch < 7) { CP_WAIT1(); } else { CP_WAIT0(); }
        __syncthreads();
        if (ch + 2 < 8) K1_ISSUE(ch + 2);

        __nv_bfloat16* ash = (__nv_bfloat16*)(sm + s * K1_ST);
        __nv_bfloat16* asl = (__nv_bfloat16*)(sm + s * K1_ST + K1_OAL);
        __nv_bfloat16* bsh = (__nv_bfloat16*)(sm + s * K1_ST + K1_OBH);
        __nv_bfloat16* bsl = (__nv_bfloat16*)(sm + s * K1_ST + K1_OBL);

#pragma unroll
        for (int ks = 0; ks < 4; ks++) {
            int kk = ks * 16;
            wmma::fragment<wmma::matrix_a, 16, 16, 16, __nv_bfloat16, wmma::row_major> ah[2], al[2];
            wmma::fragment<wmma::matrix_b, 16, 16, 16, __nv_bfloat16, wmma::row_major> bh[4], bl[4];
#pragma unroll
            for (int i = 0; i < 2; i++) {
                wmma::load_matrix_sync(ah[i], ash + (wr * 32 + i * 16) * K1_LDA + kk, K1_LDA);
                wmma::load_matrix_sync(al[i], asl + (wr * 32 + i * 16) * K1_LDA + kk, K1_LDA);
            }
#pragma unroll
            for (int j = 0; j < 4; j++) {
                wmma::load_matrix_sync(bh[j], bsh + kk * K1_LDB + wc * 64 + j * 16, K1_LDB);
                wmma::load_matrix_sync(bl[j], bsl + kk * K1_LDB + wc * 64 + j * 16, K1_LDB);
            }
            // product-major: 3 passes of 8 independent MMAs
#pragma unroll
            for (int j = 0; j < 4; j++)
#pragma unroll
                for (int i = 0; i < 2; i++)
                    wmma::mma_sync(c[i][j], ah[i], bh[j], c[i][j]);
#pragma unroll
            for (int j = 0; j < 4; j++)
#pragma unroll
                for (int i = 0; i < 2; i++)
                    wmma::mma_sync(c[i][j], ah[i], bl[j], c[i][j]);
#pragma unroll
            for (int j = 0; j < 4; j++)
#pragma unroll
                for (int i = 0; i < 2; i++)
                    wmma::mma_sync(c[i][j], al[i], bh[j], c[i][j]);
        }
        __syncthreads();
    }

    a_sh[tid] = an[(size_t)ph * 2 * NHID + tid];
#pragma unroll
    for (int i = 0; i < 2; i++)
#pragma unroll
        for (int j = 0; j < 4; j++)
            wmma::store_matrix_sync(csh + (wr * 32 + i * 16) * K1_LDC + wc * 64 + j * 16,
                                    c[i][j], K1_LDC, wmma::mem_row_major);
    __syncthreads();

    {
        int r = tid & 127, hf = tid >> 7;
        float ps = 0.f, pd = 0.f;
        const float* row = csh + r * K1_LDC + hf * 64;
#pragma unroll
        for (int i = 0; i < 64; i++) {
            float v = row[i];
            ps += v * a_sh[hf * 64 + i];
            pd += v * a_sh[NHID + hf * 64 + i];
        }
        red_s[hf * 128 + r] = ps;
        red_d[hf * 128 + r] = pd;
    }

    {
        int d = tid & 127, hf = tid >> 7;
        __nv_bfloat16* dstH = g_hThi + ((size_t)ph * NHID + d) * NN + row0 + hf * 64;
        __nv_bfloat16* dstL = g_hTlo + ((size_t)ph * NHID + d) * NN + row0 + hf * 64;
#pragma unroll
        for (int i = 0; i < 64; i += 4) {
            float v0 = csh[(hf * 64 + i    ) * K1_LDC + d];
            float v1 = csh[(hf * 64 + i + 1) * K1_LDC + d];
            float v2 = csh[(hf * 64 + i + 2) * K1_LDC + d];
            float v3 = csh[(hf * 64 + i + 3) * K1_LDC + d];
            __nv_bfloat162 h01 = __float22bfloat162_rn(make_float2(v0, v1));
            __nv_bfloat162 h23 = __float22bfloat162_rn(make_float2(v2, v3));
            __nv_bfloat162 l01 = __float22bfloat162_rn(make_float2(v0 - __bfloat162float(h01.x),
                                                                   v1 - __bfloat162float(h01.y)));
            __nv_bfloat162 l23 = __float22bfloat162_rn(make_float2(v2 - __bfloat162float(h23.x),
                                                                   v3 - __bfloat162float(h23.y)));
            *(uint2*)(dstH + i) = make_uint2(b2u(h01), b2u(h23));
            *(uint2*)(dstL + i) = make_uint2(b2u(l01), b2u(l23));
        }
    }
    __syncthreads();
    if (tid < 128) {
        float s = red_s[tid] + red_s[128 + tid];
        float d = red_d[tid] + red_d[128 + tid];
        int idx = ph * NN + row0 + tid;
        g_sE4[idx] = make_float4(s, expf(s), expf(ALPHA * s), 0.f);
        g_dE4[idx] = make_float4(d, expf(d), expf(ALPHA * d), 0.f);
    }
}

// ---------------- k3: warp-specialized, 3-stage, product-major MMA ------------
#define LDA      72
#define LDC      132
#define NSTAGE   3
#define ST_STRIDE 73728
#define OFF_SAL  18432
#define OFF_SBH  36864
#define OFF_SBL  55296
#define OFF_DE   221184
#define OFF_ROW  224256
#define OFF_MBAR 224768
#define K3_SMEM_BYTES 225280

__global__ __launch_bounds__(384, 1) void k3_attn_wmma() {
    extern __shared__ char sm[];
    float*  csh  = (float*)(sm);
    float*  rsb  = (float*)(sm + OFF_ROW);
    uint32_t sbase = smem_u32(sm);
    uint32_t mbar = sbase + OFF_MBAR;

    int ph   = blockIdx.y;
    int p    = ph >> 2, head = ph & 3;
    int row0 = blockIdx.x * 128;
    int tid  = threadIdx.x;

    if (tid == 0) {
#pragma unroll
        for (int s = 0; s < NSTAGE; s++) {
            MBAR_INIT(mbar + s * 8, 128);
            MBAR_INIT(mbar + 24 + s * 8, 256);
        }
    }
    __syncthreads();

    wmma::fragment<wmma::accumulator, 16, 16, 16, float> c[2][4];

    if (tid < 128) {
        // producer
        int r = tid;
        float4 sE = g_sE4[ph * NN + row0 + r];
        const float s_r = sE.x, Es_r = sE.y, Eas_r = sE.z;
        float rs_local = 0.f;
        uint32_t phE[NSTAGE] = {0, 0, 0};

        for (int chk = 0; chk < 32; chk++) {
            int s = chk % NSTAGE;
            int m0 = chk * 64;
            if (chk >= NSTAGE) { MBAR_WAIT(mbar + 24 + s * 8, phE[s]); phE[s] ^= 1; }

            {
                const char* srcH = (const char*)(g_hThi + ((size_t)ph * NHID + r) * NN + m0);
                const char* srcL = (const char*)(g_hTlo + ((size_t)ph * NHID + r) * NN + m0);
                uint32_t dstH = sbase + s * ST_STRIDE + OFF_SBH + r * (LDA * 2);
                uint32_t dstL = sbase + s * ST_STRIDE + OFF_SBL + r * (LDA * 2);
#pragma unroll
                for (int k = 0; k < 8; k++) {
                    CP_ASYNC16(dstH + k * 16, srcH + k * 16);
                    CP_ASYNC16(dstL + k * 16, srcL + k * 16);
                }
                CP_COMMIT();
            }
            float4* dEs = (float4*)(sm + OFF_DE + s * 1024);
            if (tid < 64) dEs[tid] = g_dE4[ph * NN + m0 + tid];
            asm volatile("bar.sync 1, 128;" ::: "memory");

            {
                __nv_bfloat16* ah_ = (__nv_bfloat16*)(sm + s * ST_STRIDE) + r * LDA;
                __nv_bfloat16* al_ = (__nv_bfloat16*)(sm + s * ST_STRIDE + OFF_SAL) + r * LDA;
                const uint32_t* mwp = &g_maskN[((size_t)p * NN + row0 + r) * 64 + chk * 2];
#pragma unroll
                for (int hf = 0; hf < 2; hf++) {
                    uint32_t mw = mwp[hf];
#pragma unroll
                    for (int g4 = 0; g4 < 4; g4++) {
                        float v[8];
#pragma unroll
                        for (int j = 0; j < 8; j++) {
                            float4 q = dEs[hf * 32 + g4 * 8 + j];
                            float t = s_r + q.x;
                            float w = (t > 0.f) ? (Es_r * q.y) : (Eas_r * q.z);
                            v[j] = ((mw >> (g4 * 8 + j)) & 1u) ? w : 0.f;
                            rs_local += v[j];
                        }
                        uint32_t hw[4], lw[4];
#pragma unroll
                        for (int jj = 0; jj < 4; jj++) {
                            __nv_bfloat162 h2 = __float22bfloat162_rn(make_float2(v[2*jj], v[2*jj+1]));
                            __nv_bfloat162 l2 = __float22bfloat162_rn(
                                make_float2(v[2*jj]   - __bfloat162float(h2.x),
                                            v[2*jj+1] - __bfloat162float(h2.y)));
                            hw[jj] = b2u(h2); lw[jj] = b2u(l2);
                        }
                        *(uint4*)(ah_ + hf * 32 + g4 * 8) = make_uint4(hw[0], hw[1], hw[2], hw[3]);
                        *(uint4*)(al_ + hf * 32 + g4 * 8) = make_uint4(lw[0], lw[1], lw[2], lw[3]);
                    }
                }
            }
            CP_WAIT0();
            MBAR_ARRIVE(mbar + s * 8);
        }
        rsb[r] = rs_local;
    } else {
        // consumer
        int cw = (tid >> 5) - 4;
        int wr = cw >> 1;
        int wc = cw & 1;
        uint32_t phF[NSTAGE] = {0, 0, 0};

#pragma unroll
        for (int i = 0; i < 2; i++)
#pragma unroll
            for (int j = 0; j < 4; j++) wmma::fill_fragment(c[i][j], 0.f);

        for (int chk = 0; chk < 32; chk++) {
            int s = chk % NSTAGE;
            MBAR_WAIT(mbar + s * 8, phF[s]); phF[s] ^= 1;

            __nv_bfloat16* ash = (__nv_bfloat16*)(sm + s * ST_STRIDE);
            __nv_bfloat16* asl = (__nv_bfloat16*)(sm + s * ST_STRIDE + OFF_SAL);
            __nv_bfloat16* bsh = (__nv_bfloat16*)(sm + s * ST_STRIDE + OFF_SBH);
            __nv_bfloat16* bsl = (__nv_bfloat16*)(sm + s * ST_STRIDE + OFF_SBL);

#pragma unroll
            for (int ks = 0; ks < 4; ks++) {
                int kk = ks * 16;
                wmma::fragment<wmma::matrix_a, 16, 16, 16, __nv_bfloat16, wmma::row_major> ah[2], al[2];
                wmma::fragment<wmma::matrix_b, 16, 16, 16, __nv_bfloat16, wmma::col_major> bh[4], bl[4];
#pragma unroll
                for (int i = 0; i < 2; i++) {
                    wmma::load_matrix_sync(ah[i], ash + (wr * 32 + i * 16) * LDA + kk, LDA);
                    wmma::load_matrix_sync(al[i], asl + (wr * 32 + i * 16) * LDA + kk, LDA);
                }
#pragma unroll
                for (int j = 0; j < 4; j++) {
                    wmma::load_matrix_sync(bh[j], bsh + (wc * 64 + j * 16) * LDA + kk, LDA);
                    wmma::load_matrix_sync(bl[j], bsl + (wc * 64 + j * 16) * LDA + kk, LDA);
                }
                // product-major: 3 passes of 8 independent MMAs
#pragma unroll
                for (int j = 0; j < 4; j++)
#pragma unroll
                    for (int i = 0; i < 2; i++)
                        wmma::mma_sync(c[i][j], ah[i], bh[j], c[i][j]);
#pragma unroll
                for (int j = 0; j < 4; j++)
#pragma unroll
                    for (int i = 0; i < 2; i++)
                        wmma::mma_sync(c[i][j], ah[i], bl[j], c[i][j]);
#pragma unroll
                for (int j = 0; j < 4; j++)
#pragma unroll
                    for (int i = 0; i < 2; i++)
                        wmma::mma_sync(c[i][j], al[i], bh[j], c[i][j]);
            }
            MBAR_ARRIVE(mbar + 24 + s * 8);
        }
    }

    __syncthreads();
    if (tid >= 128) {
        int cw = (tid >> 5) - 4;
        int wr = cw >> 1, wc = cw & 1;
#pragma unroll
        for (int i = 0; i < 2; i++)
#pragma unroll
            for (int j = 0; j < 4; j++)
                wmma::store_matrix_sync(csh + (wr * 32 + i * 16) * LDC + wc * 64 + j * 16,
                                        c[i][j], LDC, wmma::mem_row_major);
    }
    __syncthreads();

    if (tid < 256) {
        int rr  = tid & 127;
        int chf = tid >> 7;
        float rsum = rsb[rr];
        float inv = (rsum > 0.f) ? (1.f / rsum) : 0.f;
        const float* src = csh + rr * LDC + chf * 64;
        float* dst = g_m + ((size_t)p * NN + row0 + rr) * (NHEADS * NHID) + head * NHID + chf * 64;
#pragma unroll
        for (int cc = 0; cc < 64; cc += 4) {
            float f0 = src[cc]   * inv;
            float f1 = src[cc+1] * inv;
            float f2 = src[cc+2] * inv;
            float f3 = src[cc+3] * inv;
            f0 = (f0 > 0.f) ? f0 : expm1f(f0);
            f1 = (f1 > 0.f) ? f1 : expm1f(f1);
            f2 = (f2 > 0.f) ? f2 : expm1f(f2);
            f3 = (f3 > 0.f) ? f3 : expm1f(f3);
            *(float4*)(dst + cc) = make_float4(f0, f1, f2, f3);
        }
    }
}

// ---------------- k4: semantic scores ----------------
__global__ __launch_bounds__(256) void k4_sem(const float* __restrict__ Wsem,
                                              const float* __restrict__ bsem,
                                              const float* __restrict__ qsem) {
    __shared__ float msh[32][65];
    __shared__ float wsh[64 * 128];
    __shared__ float red[8];
    int row0 = blockIdx.x * 32;
    int pidx = row0 / NN;
    int tid = threadIdx.x;
    int rg = tid >> 5;
    int cg = tid & 31;

    float acc[4][4];
#pragma unroll
    for (int r = 0; r < 4; r++)
#pragma unroll
        for (int c = 0; c < 4; c++) acc[r][c] = 0.f;

    for (int k0 = 0; k0 < 512; k0 += 64) {
        for (int i = tid; i < 32 * 64; i += 256)
            msh[i >> 6][i & 63] = g_m[(size_t)(row0 + (i >> 6)) * 512 + k0 + (i & 63)];
        for (int i = tid * 4; i < 64 * 128; i += 1024)
            *(float4*)&wsh[i] = *(const float4*)&Wsem[(size_t)k0 * 128 + i];
        __syncthreads();
#pragma unroll
        for (int k = 0; k < 64; k++) {
            float mv[4];
#pragma unroll
            for (int r = 0; r < 4; r++) mv[r] = msh[rg * 4 + r][k];
            float4 wv = *(float4*)&wsh[k * 128 + cg * 4];
            float wva[4] = {wv.x, wv.y, wv.z, wv.w};
#pragma unroll
            for (int r = 0; r < 4; r++)
#pragma unroll
                for (int c = 0; c < 4; c++) acc[r][c] += mv[r] * wva[c];
        }
        __syncthreads();
    }
    float part = 0.f;
#pragma unroll
    for (int c = 0; c < 4; c++) {
        int col = cg * 4 + c;
        float b = bsem[col], q = qsem[col];
#pragma unroll
        for (int r = 0; r < 4; r++)
            part += tanhf(acc[r][c] + b) * q;
    }
#pragma unroll
    for (int off = 16; off; off >>= 1)
        part += __shfl_xor_sync(0xffffffffu, part, off);
    if ((tid & 31) == 0) red[tid >> 5] = part;
    __syncthreads();
    if (tid == 0) {
        float tot = 0.f;
#pragma unroll
        for (int i = 0; i < 8; i++) tot += red[i];
        atomicAdd(&g_scores[pidx], tot);
    }
}

// ---------------- k6 ----------------
__global__ __launch_bounds__(256) void k6_out(float* __restrict__ out) {
    __shared__ float w[NP];
    if (threadIdx.x == 0) {
        float s0 = g_scores[0] * (1.f / NN);
        float s1 = g_scores[1] * (1.f / NN);
        float s2 = g_scores[2] * (1.f / NN);
        float mx = fmaxf(s0, fmaxf(s1, s2));
        float e0 = expf(s0 - mx), e1 = expf(s1 - mx), e2 = expf(s2 - mx);
        float inv = 1.f / (e0 + e1 + e2);
        w[0] = e0 * inv; w[1] = e1 * inv; w[2] = e2 * inv;
    }
    __syncthreads();
    size_t i = (size_t)blockIdx.x * blockDim.x + threadIdx.x;
    const size_t stride = (size_t)NN * 512;
    out[i] = w[0] * g_m[i] + w[1] * g_m[stride + i] + w[2] * g_m[2 * stride + i];
}

// ---------------- launch ----------------
extern "C" void kernel_launch(void* const* d_in, const int* in_sizes, int n_in,
                              void* d_out, int out_size) {
    const float* x    = (const float*)d_in[0];
    const float* adjs = (const float*)d_in[1];
    const float* Wn   = (const float*)d_in[2];
    const float* an   = (const float*)d_in[3];
    const float* Wsem = (const float*)d_in[4];
    const float* bsem = (const float*)d_in[5];
    const float* qsem = (const float*)d_in[6];
    float* out = (float*)d_out;

    cudaFuncSetAttribute(k3_attn_wmma, cudaFuncAttributeMaxDynamicSharedMemorySize, K3_SMEM_BYTES);
    cudaFuncSetAttribute(k1_node_wmma, cudaFuncAttributeMaxDynamicSharedMemorySize, K1_SMEM_BYTES);

    k0_init<<<1, 32>>>();
    k_prep<<<PACK_BLOCKS, 256>>>(x, Wn, adjs);
    k1_node_wmma<<<dim3(NN / 128, PH), 256, K1_SMEM_BYTES>>>(an);
    k3_attn_wmma<<<dim3(NN / 128, PH), 384, K3_SMEM_BYTES>>>();   // profiled slot
    k4_sem<<<(NP * NN) / 32, 256>>>(Wsem, bsem, qsem);
    k6_out<<<(NN * 512) / 256, 256>>>(out);
}

// round 13
// speedup vs baseline: 1.0372x; 1.0319x over previous
#include <cuda_runtime.h>
#include <cuda_bf16.h>
#include <mma.h>
#include <math.h>
#include <stdint.h>
#include <string.h>

using namespace nvcuda;

#define NN     2048
#define NFEAT  512
#define NHID   128
#define NHEADS 4
#define NP     3
#define PH     (NP*NHEADS)
#define ALPHA  0.2f

// ---------------- device scratch ----------------
__device__ float g_m[NP * NN * (NHEADS*NHID)];
__device__ __align__(16) __nv_bfloat16 g_hThi[PH * NHID * NN];
__device__ __align__(16) __nv_bfloat16 g_hTlo[PH * NHID * NN];
__device__ __align__(16) __nv_bfloat16 g_xhi[NN * NFEAT];
__device__ __align__(16) __nv_bfloat16 g_xlo[NN * NFEAT];
__device__ __align__(16) __nv_bfloat16 g_Whi[PH * NFEAT * NHID];
__device__ __align__(16) __nv_bfloat16 g_Wlo[PH * NFEAT * NHID];
__device__ float4  g_sE4[PH * NN];     // (e^s, e^{as}, e^{-s}, -)
__device__ float2  g_dE2[PH * NN];     // (e^d, e^{ad})
__device__ uint32_t g_maskN[NP * NN * (NN/32)];
__device__ float g_scores[NP];

static __device__ __forceinline__ uint32_t b2u(__nv_bfloat162 h) {
    uint32_t u; memcpy(&u, &h, 4); return u;
}
static __device__ __forceinline__ uint32_t smem_u32(const void* p) {
    uint32_t a;
    asm("{ .reg .u64 t; cvta.to.shared.u64 t, %1; cvt.u32.u64 %0, t; }" : "=r"(a) : "l"(p));
    return a;
}
#define MBAR_INIT(a, c)  asm volatile("mbarrier.init.shared.b64 [%0], %1;" :: "r"((uint32_t)(a)), "r"((uint32_t)(c)) : "memory")
#define MBAR_ARRIVE(a)   asm volatile("mbarrier.arrive.shared.b64 _, [%0];" :: "r"((uint32_t)(a)) : "memory")
#define MBAR_WAIT(a, par) do { \
    uint32_t _m = (uint32_t)(a), _p = (uint32_t)(par), _d; \
    asm volatile("{\n\t.reg .pred p;\n\tmbarrier.try_wait.parity.acquire.cta.shared::cta.b64 p, [%1], %2;\n\tselp.b32 %0, 1, 0, p;\n\t}" \
                 : "=r"(_d) : "r"(_m), "r"(_p) : "memory"); \
    if (!_d) { \
        asm volatile("{\n\t.reg .pred P1;\n\tWL_%=:\n\tmbarrier.try_wait.parity.acquire.cta.shared::cta.b64 P1, [%0], %1, 0x989680;\n\t@P1 bra.uni WD_%=;\n\tbra.uni WL_%=;\n\tWD_%=:\n\t}" \
                     :: "r"(_m), "r"(_p) : "memory"); \
    } \
} while (0)
#define CP_ASYNC16(smem, gptr) \
    asm volatile("cp.async.cg.shared.global [%0], [%1], 16;" :: "r"((uint32_t)(smem)), "l"(gptr) : "memory")
#define CP_COMMIT()  asm volatile("cp.async.commit_group;" ::: "memory")
#define CP_WAIT0()   asm volatile("cp.async.wait_group 0;" ::: "memory")
#define CP_WAIT1()   asm volatile("cp.async.wait_group 1;" ::: "memory")

// ---------------- k0 ----------------
__global__ void k0_init() { if (threadIdx.x < NP) g_scores[threadIdx.x] = 0.f; }

// ---------------- k_prep: fused split + pack ----------
#define NXE (NN * NFEAT)
#define NWE (PH * NFEAT * NHID)
#define SPLIT_BLOCKS ((NXE + NWE + 255) / 256)
#define PACK_BLOCKS  (NP * NN * 64 / 8)
__global__ __launch_bounds__(256) void k_prep(const float* __restrict__ x,
                                              const float* __restrict__ Wn,
                                              const float* __restrict__ adjs) {
    {
        int g = blockIdx.x * 8 + (threadIdx.x >> 5);
        int lane = threadIdx.x & 31;
        float v = adjs[(size_t)g * 32 + lane];
        uint32_t b = __ballot_sync(0xffffffffu, v > 0.f);
        if (lane == 0) g_maskN[g] = b;
    }
    if (blockIdx.x < SPLIT_BLOCKS) {
        int i = blockIdx.x * 256 + threadIdx.x;
        if (i < NXE) {
            float v = x[i];
            __nv_bfloat16 h = __float2bfloat16_rn(v);
            g_xhi[i] = h;
            g_xlo[i] = __float2bfloat16_rn(v - __bfloat162float(h));
        }
        int j = i - NXE;
        if (j >= 0 && j < NWE) {
            float v = Wn[j];
            __nv_bfloat16 h = __float2bfloat16_rn(v);
            g_Whi[j] = h;
            g_Wlo[j] = __float2bfloat16_rn(v - __bfloat162float(h));
        }
    }
}

// ---------------- k1: 3-stage cp.async pipelined WMMA node GEMM ---------------
#define K1_LDA   72
#define K1_LDB   136
#define K1_LDC   132
#define K1_ST    71680
#define K1_OAL   18432
#define K1_OBH   36864
#define K1_OBL   54272
#define K1_OAN   215040
#define K1_ORS   216064
#define K1_ORD   217088
#define K1_SMEM_BYTES 218112

__global__ __launch_bounds__(256) void k1_node_wmma(const float* __restrict__ an) {
    extern __shared__ char sm[];
    uint32_t sbase = smem_u32(sm);
    float* csh   = (float*)(sm);
    float* a_sh  = (float*)(sm + K1_OAN);
    float* red_s = (float*)(sm + K1_ORS);
    float* red_d = (float*)(sm + K1_ORD);

    int ph   = blockIdx.y;
    int row0 = blockIdx.x * 128;
    int tid  = threadIdx.x;
    int warp = tid >> 5;
    int wr   = warp >> 1;
    int wc   = warp & 1;

    int rA = tid >> 1, hA = tid & 1;
    int rB = tid >> 2, qB = tid & 3;

    const char* xsrcH = (const char*)(g_xhi + (size_t)(row0 + rA) * NFEAT + hA * 32);
    const char* xsrcL = (const char*)(g_xlo + (size_t)(row0 + rA) * NFEAT + hA * 32);
    const char* wsrcH = (const char*)(g_Whi + (size_t)ph * NFEAT * NHID + (size_t)rB * NHID + qB * 32);
    const char* wsrcL = (const char*)(g_Wlo + (size_t)ph * NFEAT * NHID + (size_t)rB * NHID + qB * 32);
    uint32_t adstH = sbase + rA * (K1_LDA * 2) + hA * 64;
    uint32_t adstL = adstH + K1_OAL;
    uint32_t bdstH = sbase + K1_OBH + rB * (K1_LDB * 2) + qB * 64;
    uint32_t bdstL = bdstH + (K1_OBL - K1_OBH);

#define K1_ISSUE(c) do { \
    int _s = (c) % 3; uint32_t _sb = _s * K1_ST; size_t _ko = (size_t)(c) * 64; \
    const char* _xh = xsrcH + _ko * 2; const char* _xl = xsrcL + _ko * 2; \
    const char* _wh = wsrcH + _ko * NHID * 2; const char* _wl = wsrcL + _ko * NHID * 2; \
    CP_ASYNC16(adstH + _sb,      _xh);      CP_ASYNC16(adstH + _sb + 16, _xh + 16); \
    CP_ASYNC16(adstH + _sb + 32, _xh + 32); CP_ASYNC16(adstH + _sb + 48, _xh + 48); \
    CP_ASYNC16(adstL + _sb,      _xl);      CP_ASYNC16(adstL + _sb + 16, _xl + 16); \
    CP_ASYNC16(adstL + _sb + 32, _xl + 32); CP_ASYNC16(adstL + _sb + 48, _xl + 48); \
    CP_ASYNC16(bdstH + _sb,      _wh);      CP_ASYNC16(bdstH + _sb + 16, _wh + 16); \
    CP_ASYNC16(bdstH + _sb + 32, _wh + 32); CP_ASYNC16(bdstH + _sb + 48, _wh + 48); \
    CP_ASYNC16(bdstL + _sb,      _wl);      CP_ASYNC16(bdstL + _sb + 16, _wl + 16); \
    CP_ASYNC16(bdstL + _sb + 32, _wl + 32); CP_ASYNC16(bdstL + _sb + 48, _wl + 48); \
    CP_COMMIT(); \
} while (0)

    wmma::fragment<wmma::accumulator, 16, 16, 16, float> c[2][4];
#pragma unroll
    for (int i = 0; i < 2; i++)
#pragma unroll
        for (int j = 0; j < 4; j++) wmma::fill_fragment(c[i][j], 0.f);

    K1_ISSUE(0);
    K1_ISSUE(1);

    for (int ch = 0; ch < 8; ch++) {
        int s = ch % 3;
        if (ch < 7) { CP_WAIT1(); } else { CP_WAIT0(); }
        __syncthreads();
        if (ch + 2 < 8) K1_ISSUE(ch + 2);

        __nv_bfloat16* ash = (__nv_bfloat16*)(sm + s * K1_ST);
        __nv_bfloat16* asl = (__nv_bfloat16*)(sm + s * K1_ST + K1_OAL);
        __nv_bfloat16* bsh = (__nv_bfloat16*)(sm + s * K1_ST + K1_OBH);
        __nv_bfloat16* bsl = (__nv_bfloat16*)(sm + s * K1_ST + K1_OBL);

#pragma unroll
        for (int ks = 0; ks < 4; ks++) {
            int kk = ks * 16;
            wmma::fragment<wmma::matrix_a, 16, 16, 16, __nv_bfloat16, wmma::row_major> ah[2], al[2];
            wmma::fragment<wmma::matrix_b, 16, 16, 16, __nv_bfloat16, wmma::row_major> bh[4], bl[4];
#pragma unroll
            for (int i = 0; i < 2; i++) {
                wmma::load_matrix_sync(ah[i], ash + (wr * 32 + i * 16) * K1_LDA + kk, K1_LDA);
                wmma::load_matrix_sync(al[i], asl + (wr * 32 + i * 16) * K1_LDA + kk, K1_LDA);
            }
#pragma unroll
            for (int j = 0; j < 4; j++) {
                wmma::load_matrix_sync(bh[j], bsh + kk * K1_LDB + wc * 64 + j * 16, K1_LDB);
                wmma::load_matrix_sync(bl[j], bsl + kk * K1_LDB + wc * 64 + j * 16, K1_LDB);
            }
#pragma unroll
            for (int j = 0; j < 4; j++)
#pragma unroll
                for (int i = 0; i < 2; i++)
                    wmma::mma_sync(c[i][j], ah[i], bh[j], c[i][j]);
#pragma unroll
            for (int j = 0; j < 4; j++)
#pragma unroll
                for (int i = 0; i < 2; i++)
                    wmma::mma_sync(c[i][j], ah[i], bl[j], c[i][j]);
#pragma unroll
            for (int j = 0; j < 4; j++)
#pragma unroll
                for (int i = 0; i < 2; i++)
                    wmma::mma_sync(c[i][j], al[i], bh[j], c[i][j]);
        }
        __syncthreads();
    }

    a_sh[tid] = an[(size_t)ph * 2 * NHID + tid];
#pragma unroll
    for (int i = 0; i < 2; i++)
#pragma unroll
        for (int j = 0; j < 4; j++)
            wmma::store_matrix_sync(csh + (wr * 32 + i * 16) * K1_LDC + wc * 64 + j * 16,
                                    c[i][j], K1_LDC, wmma::mem_row_major);
    __syncthreads();

    {
        int r = tid & 127, hf = tid >> 7;
        float ps = 0.f, pd = 0.f;
        const float* row = csh + r * K1_LDC + hf * 64;
#pragma unroll
        for (int i = 0; i < 64; i++) {
            float v = row[i];
            ps += v * a_sh[hf * 64 + i];
            pd += v * a_sh[NHID + hf * 64 + i];
        }
        red_s[hf * 128 + r] = ps;
        red_d[hf * 128 + r] = pd;
    }

    {
        int d = tid & 127, hf = tid >> 7;
        __nv_bfloat16* dstH = g_hThi + ((size_t)ph * NHID + d) * NN + row0 + hf * 64;
        __nv_bfloat16* dstL = g_hTlo + ((size_t)ph * NHID + d) * NN + row0 + hf * 64;
#pragma unroll
        for (int i = 0; i < 64; i += 4) {
            float v0 = csh[(hf * 64 + i    ) * K1_LDC + d];
            float v1 = csh[(hf * 64 + i + 1) * K1_LDC + d];
            float v2 = csh[(hf * 64 + i + 2) * K1_LDC + d];
            float v3 = csh[(hf * 64 + i + 3) * K1_LDC + d];
            __nv_bfloat162 h01 = __float22bfloat162_rn(make_float2(v0, v1));
            __nv_bfloat162 h23 = __float22bfloat162_rn(make_float2(v2, v3));
            __nv_bfloat162 l01 = __float22bfloat162_rn(make_float2(v0 - __bfloat162float(h01.x),
                                                                   v1 - __bfloat162float(h01.y)));
            __nv_bfloat162 l23 = __float22bfloat162_rn(make_float2(v2 - __bfloat162float(h23.x),
                                                                   v3 - __bfloat162float(h23.y)));
            *(uint2*)(dstH + i) = make_uint2(b2u(h01), b2u(h23));
            *(uint2*)(dstL + i) = make_uint2(b2u(l01), b2u(l23));
        }
    }
    __syncthreads();
    if (tid < 128) {
        float s = red_s[tid] + red_s[128 + tid];
        float d = red_d[tid] + red_d[128 + tid];
        int idx = ph * NN + row0 + tid;
        g_sE4[idx] = make_float4(expf(s), expf(ALPHA * s), expf(-s), 0.f);
        g_dE2[idx] = make_float2(expf(d), expf(ALPHA * d));
    }
}

// ---------------- k3: 8 producer warps + 8 consumer warps, 3 stages -----------
#define LDA      72
#define LDC      132
#define NSTAGE   3
#define ST_STRIDE 73728
#define OFF_SAL  18432
#define OFF_SBH  36864
#define OFF_SBL  55296
#define OFF_DE   221184
#define OFF_ROW  222720
#define OFF_MBAR 223744
#define K3_SMEM_BYTES 224256

__global__ __launch_bounds__(512, 1) void k3_attn_wmma() {
    extern __shared__ char sm[];
    float*  csh  = (float*)(sm);
    float*  rsb  = (float*)(sm + OFF_ROW);
    uint32_t sbase = smem_u32(sm);
    uint32_t mbar = sbase + OFF_MBAR;

    int ph   = blockIdx.y;
    int p    = ph >> 2, head = ph & 3;
    int row0 = blockIdx.x * 128;
    int tid  = threadIdx.x;

    if (tid == 0) {
#pragma unroll
        for (int s = 0; s < NSTAGE; s++) {
            MBAR_INIT(mbar + s * 8, 256);        // full: 256 producers arrive
            MBAR_INIT(mbar + 24 + s * 8, 256);   // empty: 256 consumers arrive
        }
    }
    __syncthreads();

    wmma::fragment<wmma::accumulator, 16, 16, 16, float> c[2][4];

    if (tid < 256) {
        // ================= PRODUCER (8 warps, 2 threads/row) =================
        int r    = tid >> 1;
        int half = tid & 1;
        float4 sE = g_sE4[ph * NN + row0 + r];
        const float Es_r = sE.x, Eas_r = sE.y, En_r = sE.z;
        float rs_local = 0.f;
        uint32_t phE[NSTAGE] = {0, 0, 0};

        for (int chk = 0; chk < 32; chk++) {
            int s = chk % NSTAGE;
            int m0 = chk * 64;
            if (chk >= NSTAGE) { MBAR_WAIT(mbar + 24 + s * 8, phE[s]); phE[s] ^= 1; }

            {   // B tile: 2 threads per d-row, 32 m each (4x16B hi + 4x16B lo)
                const char* srcH = (const char*)(g_hThi + ((size_t)ph * NHID + r) * NN + m0 + half * 32);
                const char* srcL = (const char*)(g_hTlo + ((size_t)ph * NHID + r) * NN + m0 + half * 32);
                uint32_t dstH = sbase + s * ST_STRIDE + OFF_SBH + r * (LDA * 2) + half * 64;
                uint32_t dstL = sbase + s * ST_STRIDE + OFF_SBL + r * (LDA * 2) + half * 64;
#pragma unroll
                for (int k = 0; k < 4; k++) {
                    CP_ASYNC16(dstH + k * 16, srcH + k * 16);
                    CP_ASYNC16(dstL + k * 16, srcL + k * 16);
                }
                CP_COMMIT();
            }
            float2* dEs = (float2*)(sm + OFF_DE + s * 512);
            if (tid < 64) dEs[tid] = g_dE2[ph * NN + m0 + tid];
            asm volatile("bar.sync 1, 256;" ::: "memory");   // dE visible to producers

            {   // A tile: row r, m in [m0+half*32, +32)
                __nv_bfloat16* ah_ = (__nv_bfloat16*)(sm + s * ST_STRIDE) + r * LDA + half * 32;
                __nv_bfloat16* al_ = (__nv_bfloat16*)(sm + s * ST_STRIDE + OFF_SAL) + r * LDA + half * 32;
                uint32_t mw = g_maskN[((size_t)p * NN + row0 + r) * 64 + chk * 2 + half];
#pragma unroll
                for (int g4 = 0; g4 < 4; g4++) {
                    float v[8];
#pragma unroll
                    for (int j = 0; j < 8; j++) {
                        float2 q = dEs[half * 32 + g4 * 8 + j];
                        // s+d>0  <=>  e^d > e^{-s}
                        float w = (q.x > En_r) ? (Es_r * q.x) : (Eas_r * q.y);
                        v[j] = ((mw >> (g4 * 8 + j)) & 1u) ? w : 0.f;
                        rs_local += v[j];
                    }
                    uint32_t hw[4], lw[4];
#pragma unroll
                    for (int jj = 0; jj < 4; jj++) {
                        __nv_bfloat162 h2 = __float22bfloat162_rn(make_float2(v[2*jj], v[2*jj+1]));
                        __nv_bfloat162 l2 = __float22bfloat162_rn(
                            make_float2(v[2*jj]   - __bfloat162float(h2.x),
                                        v[2*jj+1] - __bfloat162float(h2.y)));
                        hw[jj] = b2u(h2); lw[jj] = b2u(l2);
                    }
                    *(uint4*)(ah_ + g4 * 8) = make_uint4(hw[0], hw[1], hw[2], hw[3]);
                    *(uint4*)(al_ + g4 * 8) = make_uint4(lw[0], lw[1], lw[2], lw[3]);
                }
            }
            CP_WAIT0();
            MBAR_ARRIVE(mbar + s * 8);
        }
        rsb[half * 128 + r] = rs_local;
    } else {
        // ================= CONSUMER (8 warps) =================
        int cw = (tid >> 5) - 8;     // 0..7
        int wr = cw >> 1;
        int wc = cw & 1;
        uint32_t phF[NSTAGE] = {0, 0, 0};

#pragma unroll
        for (int i = 0; i < 2; i++)
#pragma unroll
            for (int j = 0; j < 4; j++) wmma::fill_fragment(c[i][j], 0.f);

        for (int chk = 0; chk < 32; chk++) {
            int s = chk % NSTAGE;
            MBAR_WAIT(mbar + s * 8, phF[s]); phF[s] ^= 1;

            __nv_bfloat16* ash = (__nv_bfloat16*)(sm + s * ST_STRIDE);
            __nv_bfloat16* asl = (__nv_bfloat16*)(sm + s * ST_STRIDE + OFF_SAL);
            __nv_bfloat16* bsh = (__nv_bfloat16*)(sm + s * ST_STRIDE + OFF_SBH);
            __nv_bfloat16* bsl = (__nv_bfloat16*)(sm + s * ST_STRIDE + OFF_SBL);

#pragma unroll
            for (int ks = 0; ks < 4; ks++) {
                int kk = ks * 16;
                wmma::fragment<wmma::matrix_a, 16, 16, 16, __nv_bfloat16, wmma::row_major> ah[2], al[2];
                wmma::fragment<wmma::matrix_b, 16, 16, 16, __nv_bfloat16, wmma::col_major> bh[4], bl[4];
#pragma unroll
                for (int i = 0; i < 2; i++) {
                    wmma::load_matrix_sync(ah[i], ash + (wr * 32 + i * 16) * LDA + kk, LDA);
                    wmma::load_matrix_sync(al[i], asl + (wr * 32 + i * 16) * LDA + kk, LDA);
                }
#pragma unroll
                for (int j = 0; j < 4; j++) {
                    wmma::load_matrix_sync(bh[j], bsh + (wc * 64 + j * 16) * LDA + kk, LDA);
                    wmma::load_matrix_sync(bl[j], bsl + (wc * 64 + j * 16) * LDA + kk, LDA);
                }
#pragma unroll
                for (int j = 0; j < 4; j++)
#pragma unroll
                    for (int i = 0; i < 2; i++)
                        wmma::mma_sync(c[i][j], ah[i], bh[j], c[i][j]);
#pragma unroll
                for (int j = 0; j < 4; j++)
#pragma unroll
                    for (int i = 0; i < 2; i++)
                        wmma::mma_sync(c[i][j], ah[i], bl[j], c[i][j]);
#pragma unroll
                for (int j = 0; j < 4; j++)
#pragma unroll
                    for (int i = 0; i < 2; i++)
                        wmma::mma_sync(c[i][j], al[i], bh[j], c[i][j]);
            }
            MBAR_ARRIVE(mbar + 24 + s * 8);
        }
    }

    __syncthreads();   // stages dead, rowsums visible
    if (tid >= 256) {
        int cw = (tid >> 5) - 8;
        int wr = cw >> 1, wc = cw & 1;
#pragma unroll
        for (int i = 0; i < 2; i++)
#pragma unroll
            for (int j = 0; j < 4; j++)
                wmma::store_matrix_sync(csh + (wr * 32 + i * 16) * LDC + wc * 64 + j * 16,
                                        c[i][j], LDC, wmma::mem_row_major);
    }
    __syncthreads();

    if (tid < 256) {
        int rr  = tid & 127;
        int chf = tid >> 7;
        float rsum = rsb[rr] + rsb[128 + rr];
        float inv = (rsum > 0.f) ? (1.f / rsum) : 0.f;
        const float* src = csh + rr * LDC + chf * 64;
        float* dst = g_m + ((size_t)p * NN + row0 + rr) * (NHEADS * NHID) + head * NHID + chf * 64;
#pragma unroll
        for (int cc = 0; cc < 64; cc += 4) {
            float f0 = src[cc]   * inv;
            float f1 = src[cc+1] * inv;
            float f2 = src[cc+2] * inv;
            float f3 = src[cc+3] * inv;
            f0 = (f0 > 0.f) ? f0 : expm1f(f0);
            f1 = (f1 > 0.f) ? f1 : expm1f(f1);
            f2 = (f2 > 0.f) ? f2 : expm1f(f2);
            f3 = (f3 > 0.f) ? f3 : expm1f(f3);
            *(float4*)(dst + cc) = make_float4(f0, f1, f2, f3);
        }
    }
}

// ---------------- k4: semantic scores ----------------
__global__ __launch_bounds__(256) void k4_sem(const float* __restrict__ Wsem,
                                              const float* __restrict__ bsem,
                                              const float* __restrict__ qsem) {
    __shared__ float msh[32][65];
    __shared__ float wsh[64 * 128];
    __shared__ float red[8];
    int row0 = blockIdx.x * 32;
    int pidx = row0 / NN;
    int tid = threadIdx.x;
    int rg = tid >> 5;
    int cg = tid & 31;

    float acc[4][4];
#pragma unroll
    for (int r = 0; r < 4; r++)
#pragma unroll
        for (int c = 0; c < 4; c++) acc[r][c] = 0.f;

    for (int k0 = 0; k0 < 512; k0 += 64) {
        for (int i = tid; i < 32 * 64; i += 256)
            msh[i >> 6][i & 63] = g_m[(size_t)(row0 + (i >> 6)) * 512 + k0 + (i & 63)];
        for (int i = tid * 4; i < 64 * 128; i += 1024)
            *(float4*)&wsh[i] = *(const float4*)&Wsem[(size_t)k0 * 128 + i];
        __syncthreads();
#pragma unroll
        for (int k = 0; k < 64; k++) {
            float mv[4];
#pragma unroll
            for (int r = 0; r < 4; r++) mv[r] = msh[rg * 4 + r][k];
            float4 wv = *(float4*)&wsh[k * 128 + cg * 4];
            float wva[4] = {wv.x, wv.y, wv.z, wv.w};
#pragma unroll
            for (int r = 0; r < 4; r++)
#pragma unroll
                for (int c = 0; c < 4; c++) acc[r][c] += mv[r] * wva[c];
        }
        __syncthreads();
    }
    float part = 0.f;
#pragma unroll
    for (int c = 0; c < 4; c++) {
        int col = cg * 4 + c;
        float b = bsem[col], q = qsem[col];
#pragma unroll
        for (int r = 0; r < 4; r++)
            part += tanhf(acc[r][c] + b) * q;
    }
#pragma unroll
    for (int off = 16; off; off >>= 1)
        part += __shfl_xor_sync(0xffffffffu, part, off);
    if ((tid & 31) == 0) red[tid >> 5] = part;
    __syncthreads();
    if (tid == 0) {
        float tot = 0.f;
#pragma unroll
        for (int i = 0; i < 8; i++) tot += red[i];
        atomicAdd(&g_scores[pidx], tot);
    }
}

// ---------------- k6 ----------------
__global__ __launch_bounds__(256) void k6_out(float* __restrict__ out) {
    __shared__ float w[NP];
    if (threadIdx.x == 0) {
        float s0 = g_scores[0] * (1.f / NN);
        float s1 = g_scores[1] * (1.f / NN);
        float s2 = g_scores[2] * (1.f / NN);
        float mx = fmaxf(s0, fmaxf(s1, s2));
        float e0 = expf(s0 - mx), e1 = expf(s1 - mx), e2 = expf(s2 - mx);
        float inv = 1.f / (e0 + e1 + e2);
        w[0] = e0 * inv; w[1] = e1 * inv; w[2] = e2 * inv;
    }
    __syncthreads();
    size_t i = (size_t)blockIdx.x * blockDim.x + threadIdx.x;
    const size_t stride = (size_t)NN * 512;
    out[i] = w[0] * g_m[i] + w[1] * g_m[stride + i] + w[2] * g_m[2 * stride + i];
}

// ---------------- launch ----------------
extern "C" void kernel_launch(void* const* d_in, const int* in_sizes, int n_in,
                              void* d_out, int out_size) {
    const float* x    = (const float*)d_in[0];
    const float* adjs = (const float*)d_in[1];
    const float* Wn   = (const float*)d_in[2];
    const float* an   = (const float*)d_in[3];
    const float* Wsem = (const float*)d_in[4];
    const float* bsem = (const float*)d_in[5];
    const float* qsem = (const float*)d_in[6];
    float* out = (float*)d_out;

    cudaFuncSetAttribute(k3_attn_wmma, cudaFuncAttributeMaxDynamicSharedMemorySize, K3_SMEM_BYTES);
    cudaFuncSetAttribute(k1_node_wmma, cudaFuncAttributeMaxDynamicSharedMemorySize, K1_SMEM_BYTES);

    k0_init<<<1, 32>>>();
    k_prep<<<PACK_BLOCKS, 256>>>(x, Wn, adjs);
    k1_node_wmma<<<dim3(NN / 128, PH), 256, K1_SMEM_BYTES>>>(an);
    k3_attn_wmma<<<dim3(NN / 128, PH), 512, K3_SMEM_BYTES>>>();   // profiled slot
    k4_sem<<<(NP * NN) / 32, 256>>>(Wsem, bsem, qsem);
    k6_out<<<(NN * 512) / 256, 256>>>(out);
}